// round 13
// baseline (speedup 1.0000x reference)
#include <cuda_runtime.h>
#include <cstdint>

// BinaryTree hierarchical-softmax forward:
//   z = W[leaf(input)], path = 21 root-to-leaf nodes of context vertex
//   out[b] = prod_i sigmoid(dot(W[path_i], z)) = 1 / prod_i (1 + exp(-s_i))
//
// d_in[0]: collocation int32 [65536, 2]
// d_in[1]: W float32 [2097151, 128]
// d_out  : float32 [65536]
//
// The register file has been the bottleneck because it doubles as the landing
// buffer for in-flight rows (16 warps x 22 rows x 512B = 176KB of regfile).
// Fix: the 5 true-DRAM rows per element (z + path levels 17..20) land in a
// warp-private 3-stage smem ring via cp.async, issued TWO elements ahead
// (double the flight time, ~zero register cost). Lane l copies exactly the
// 16B it later reads, so cp.async.wait_group alone orders it (no barriers).
// Levels 7..16: one-element-ahead register burst (40 regs, proven). Levels
// 0..6: JIT from L1 (127 rows = 63.5KB resident, proven). Pruned 23-shuffle
// compaction reduce after the burst. 64-thread blocks, occupancy-sized
// single-wave grid, NO register cap (R5: caps spill the burst).

#define DEPTH   20
#define NPATH   21
#define OFFSET  1048575u             // (1<<DEPTH)-1
#define BATCH   65536
#define NL2     10                   // register-burst path levels 7..16
#define RING    3                    // smem ring stages (2 in flight)

__device__ __forceinline__ void cp16(uint32_t dst, const void* src) {
    asm volatile("cp.async.cg.shared.global [%0], [%1], 16;" :: "r"(dst), "l"(src));
}

__global__ __launch_bounds__(64)
void BinaryTree_65927747993695_kernel(const int* __restrict__ coll,
                                      const float* __restrict__ W,
                                      float* __restrict__ out)
{
    // [warp-in-block][stage][row: 0=z, 1..4=levels 17..20][lane]
    __shared__ float4 ring[2][RING][5][32];

    const int tid    = blockIdx.x * blockDim.x + threadIdx.x;
    const int gw     = tid >> 5;
    const int lane   = tid & 31;
    const int wib    = (threadIdx.x >> 5) & 1;
    const int stride = (gridDim.x * blockDim.x) >> 5;

    int e = gw;
    if (e >= BATCH) return;

    // float4-unit bases; path "-1" folded into Wm1; lane slice folded in.
    const float4* __restrict__ Wl  = (const float4*)W + lane;
    const float4* __restrict__ Wm1 = Wl - 32;

    // --- prologue: coll for e, e+1s, e+2s ---
    int2 cv0 = __ldg((const int2*)coll + e);
    int  e1  = e + stride;
    int2 cv1 = make_int2(0, 0);
    if (e1 < BATCH) cv1 = __ldg((const int2*)coll + e1);
    int  e2  = e1 + stride;
    int2 cv2 = make_int2(0, 0);
    if (e2 < BATCH) cv2 = __ldg((const int2*)coll + e2);

    // deep cp.async issue for stage s / collocation cv
    auto issue_deep = [&](int s, int2 cv) {
        uint32_t dst0 = (uint32_t)__cvta_generic_to_shared(&ring[wib][s][0][lane]);
        cp16(dst0, Wl + (size_t)((unsigned)cv.x + OFFSET) * 32);
        const unsigned bb = (unsigned)cv.y + OFFSET + 1u;
#pragma unroll
        for (int j = 0; j < 4; ++j) {                // levels 17..20
            uint32_t dst = (uint32_t)__cvta_generic_to_shared(&ring[wib][s][1 + j][lane]);
            cp16(dst, Wm1 + (size_t)(bb >> (3 - j)) * 32);
        }
    };

    // stages 0 and 1 for e and e+1s (one commit group each)
    issue_deep(0, cv0);
    asm volatile("cp.async.commit_group;" ::: "memory");
    if (e1 < BATCH) issue_deep(1, cv1);
    asm volatile("cp.async.commit_group;" ::: "memory");

    // register burst: levels 7..16 of e (shift = 13-j)
    unsigned b = (unsigned)cv0.y + OFFSET + 1u;
    float4 w[NL2];
#pragma unroll
    for (int j = 0; j < NL2; ++j)
        w[j] = __ldg(Wm1 + (size_t)(b >> (13 - j)) * 32);

    int s = 0;
    for (;;) {
        // prefetch coll three elements ahead
        const int e3 = e2 + stride;
        int2 cv3 = make_int2(0, 0);
        if (e3 < BATCH) cv3 = __ldg((const int2*)coll + e3);

        // issue deep rows for e+2s into stage (s+2)%RING; always one commit
        int snext = s + 2; if (snext >= RING) snext -= RING;
        if (e2 < BATCH) issue_deep(snext, cv2);
        asm volatile("cp.async.commit_group;" ::: "memory");

        // stage s (element e) complete when <=2 groups pending
        asm volatile("cp.async.wait_group 2;" ::: "memory");

        float a[NPATH];

        // deep rows from smem: z + levels 17..20 (lane reads its own 16B)
        const float4 z   = ring[wib][s][0][lane];
        {
            const float4 d0 = ring[wib][s][1][lane];
            const float4 d1 = ring[wib][s][2][lane];
            const float4 d2 = ring[wib][s][3][lane];
            const float4 d3 = ring[wib][s][4][lane];
            a[17] = d0.x * z.x + d0.y * z.y + d0.z * z.z + d0.w * z.w;
            a[18] = d1.x * z.x + d1.y * z.y + d1.z * z.z + d1.w * z.w;
            a[19] = d2.x * z.x + d2.y * z.y + d2.z * z.z + d2.w * z.w;
            a[20] = d3.x * z.x + d3.y * z.y + d3.z * z.z + d3.w * z.w;
        }

        // shallow JIT levels 0..6 (L1 hits), 4+3 chunks
        {
            float4 h0 = __ldg(Wm1 + (size_t)(b >> DEPTH) * 32);
            float4 h1 = __ldg(Wm1 + (size_t)(b >> (DEPTH - 1)) * 32);
            float4 h2 = __ldg(Wm1 + (size_t)(b >> (DEPTH - 2)) * 32);
            float4 h3 = __ldg(Wm1 + (size_t)(b >> (DEPTH - 3)) * 32);
            a[0] = h0.x * z.x + h0.y * z.y + h0.z * z.z + h0.w * z.w;
            a[1] = h1.x * z.x + h1.y * z.y + h1.z * z.z + h1.w * z.w;
            a[2] = h2.x * z.x + h2.y * z.y + h2.z * z.z + h2.w * z.w;
            a[3] = h3.x * z.x + h3.y * z.y + h3.z * z.z + h3.w * z.w;
        }
        {
            float4 h4 = __ldg(Wm1 + (size_t)(b >> (DEPTH - 4)) * 32);
            float4 h5 = __ldg(Wm1 + (size_t)(b >> (DEPTH - 5)) * 32);
            float4 h6 = __ldg(Wm1 + (size_t)(b >> (DEPTH - 6)) * 32);
            a[4] = h4.x * z.x + h4.y * z.y + h4.z * z.z + h4.w * z.w;
            a[5] = h5.x * z.x + h5.y * z.y + h5.z * z.z + h5.w * z.w;
            a[6] = h6.x * z.x + h6.y * z.y + h6.z * z.z + h6.w * z.w;
        }

        // mid levels 7..16 from the register burst (frees w[])
#pragma unroll
        for (int j = 0; j < NL2; ++j)
            a[7 + j] = w[j].x * z.x + w[j].y * z.y + w[j].z * z.z + w[j].w * z.w;

        // next element's register burst into the freed registers
        const bool have_next = (e1 < BATCH);
        if (have_next) {
            const unsigned bn = (unsigned)cv1.y + OFFSET + 1u;
#pragma unroll
            for (int j = 0; j < NL2; ++j)
                w[j] = __ldg(Wm1 + (size_t)(bn >> (13 - j)) * 32);
            b = bn;
        }

        // --- pruned compaction transpose-reduce (23 shuffles) ---
        // out-of-range partner slots (21, 22, 24) are explicit zeros.
        {
            const bool hi = (lane & 1) != 0;
#pragma unroll
            for (int k = 0; k < 20; k += 2) {
                const float send = hi ? a[k] : a[k + 1];
                const float recv = __shfl_xor_sync(0xFFFFFFFFu, send, 1);
                a[k] = (hi ? a[k + 1] : a[k]) + recv;
            }
            {
                const float send = hi ? a[20] : 0.0f;
                const float recv = __shfl_xor_sync(0xFFFFFFFFu, send, 1);
                a[20] = (hi ? 0.0f : a[20]) + recv;
            }
        }
        {
            const bool hi = (lane & 2) != 0;
#pragma unroll
            for (int k = 0; k < 20; k += 4) {
                const float send = hi ? a[k] : a[k + 2];
                const float recv = __shfl_xor_sync(0xFFFFFFFFu, send, 2);
                a[k] = (hi ? a[k + 2] : a[k]) + recv;
            }
            {
                const float send = hi ? a[20] : 0.0f;
                const float recv = __shfl_xor_sync(0xFFFFFFFFu, send, 2);
                a[20] = (hi ? 0.0f : a[20]) + recv;
            }
        }
        {
            const bool hi = (lane & 4) != 0;
#pragma unroll
            for (int k = 0; k < 24; k += 8) {       // k = 0, 8, 16
                const float send = hi ? a[k] : a[k + 4];
                const float recv = __shfl_xor_sync(0xFFFFFFFFu, send, 4);
                a[k] = (hi ? a[k + 4] : a[k]) + recv;
            }
        }
        {
            const bool hi = (lane & 8) != 0;
            {
                const float send = hi ? a[0] : a[8];
                const float recv = __shfl_xor_sync(0xFFFFFFFFu, send, 8);
                a[0] = (hi ? a[8] : a[0]) + recv;
            }
            {
                const float send = hi ? a[16] : 0.0f;
                const float recv = __shfl_xor_sync(0xFFFFFFFFu, send, 8);
                a[16] = (hi ? 0.0f : a[16]) + recv;
            }
        }
        {
            const bool hi = (lane & 16) != 0;
            const float send = hi ? a[0] : a[16];
            const float recv = __shfl_xor_sync(0xFFFFFFFFu, send, 16);
            a[0] = (hi ? a[16] : a[0]) + recv;
        }

        // lane l (< 21) holds s_l; one SIMT EX2 covers all levels
        float c = (lane < NPATH) ? (1.0f + __expf(-a[0])) : 1.0f;
#pragma unroll
        for (int o = 16; o > 0; o >>= 1)
            c *= __shfl_xor_sync(0xFFFFFFFFu, c, o);

        if (lane == 0) out[e] = __fdividef(1.0f, c);

        if (!have_next) return;
        e   = e1;
        e1  = e2;
        e2  = e3;
        cv1 = cv2;
        cv2 = cv3;
        s   = s + 1; if (s >= RING) s -= RING;
    }
}

extern "C" void kernel_launch(void* const* d_in, const int* in_sizes, int n_in,
                              void* d_out, int out_size)
{
    const int*   coll = (const int*)d_in[0];
    const float* W    = (const float*)d_in[1];
    float*       out  = (float*)d_out;

    // 2-warp blocks; exactly one resident wave sized from measured occupancy.
    const int threads = 64;
    int bpsm = 8;
    cudaOccupancyMaxActiveBlocksPerMultiprocessor(
        &bpsm, BinaryTree_65927747993695_kernel, threads, 0);
    if (bpsm < 1) bpsm = 1;
    long long blocks = (long long)bpsm * 148;
    if (blocks > BATCH / 2) blocks = BATCH / 2;
    BinaryTree_65927747993695_kernel<<<(int)blocks, threads>>>(coll, W, out);
}

// round 14
// speedup vs baseline: 1.0428x; 1.0428x over previous
#include <cuda_runtime.h>
#include <cstdint>

// BinaryTree hierarchical-softmax forward:
//   z = W[leaf(input)], path = 21 root-to-leaf nodes of context vertex
//   out[b] = prod_i sigmoid(dot(W[path_i], z)) = 1 / prod_i (1 + exp(-s_i))
//
// d_in[0]: collocation int32 [65536, 2]
// d_in[1]: W float32 [2097151, 128]
// d_out  : float32 [65536]
//
// Three-tier latency-matched pipeline (throughput law: T_iter =
// max(compute, exposed latency); HBM = bytes_per_iter / T_iter):
//   deep  (z + levels 17..20, true DRAM set): 2-elements-ahead,
//         double-buffered registers -> flight = 2*T_iter, never exposed.
//   mid   (levels 7..16, L2-resident):        1-element-ahead burst.
//   shallow (levels 0..6, L1-resident):       JIT in 4+3 chunks.
// Reduction via warp-private padded smem transpose (STS partials as they
// are computed -> no live a[21] array, ~zero register cost). 64-thread
// blocks (linear reg->warp tradeoff), occupancy-sized single-wave grid,
// NO register cap (R5: caps spill the bursts).

#define DEPTH   20
#define NPATH   21
#define OFFSET  1048575u             // (1<<DEPTH)-1
#define BATCH   65536
#define NMID    10                   // levels 7..16
#define PITCH   36                   // floats; rows 16B-aligned, low conflict

__global__ __launch_bounds__(64)
void BinaryTree_65927747993695_kernel(const int* __restrict__ coll,
                                      const float* __restrict__ W,
                                      float* __restrict__ out)
{
    __shared__ float red[2][NPATH * PITCH];

    const int tid    = blockIdx.x * blockDim.x + threadIdx.x;
    const int gw     = tid >> 5;
    const int lane   = tid & 31;
    const int wib    = (threadIdx.x >> 5) & 1;
    const int stride = (gridDim.x * blockDim.x) >> 5;

    if (gw >= BATCH) return;
    int e = gw;

    float* __restrict__ row = red[wib];
    const int2* __restrict__ coll2 = (const int2*)coll;

    // float4-unit bases; path "-1" folded into Wm1; lane slice folded in.
    const float4* __restrict__ Wl  = (const float4*)W + lane;
    const float4* __restrict__ Wm1 = Wl - 32;

    // --- prologue: coll for e .. e+3 (clamped-safe) ---
    int2 cvt0 = __ldg(coll2 + e);
    int2 cvt1 = (e + stride     < BATCH) ? __ldg(coll2 + e + stride)     : make_int2(0, 0);
    int2 cv2  = (e + 2 * stride < BATCH) ? __ldg(coll2 + e + 2 * stride) : make_int2(0, 0);
    int2 cv3  = (e + 3 * stride < BATCH) ? __ldg(coll2 + e + 3 * stride) : make_int2(0, 0);

    unsigned b0 = (unsigned)cvt0.y + OFFSET + 1u;
    unsigned b1 = (unsigned)cvt1.y + OFFSET + 1u;

    // deep buffers: [0]=z, [1..4]=levels 17..20
    float4 dA[5], dB[5];
    {
        dA[0] = __ldg(Wl + (size_t)((unsigned)cvt0.x + OFFSET) * 32);
#pragma unroll
        for (int j = 0; j < 4; ++j)
            dA[1 + j] = __ldg(Wm1 + (size_t)(b0 >> (3 - j)) * 32);
        dB[0] = __ldg(Wl + (size_t)((unsigned)cvt1.x + OFFSET) * 32);
#pragma unroll
        for (int j = 0; j < 4; ++j)
            dB[1 + j] = __ldg(Wm1 + (size_t)(b1 >> (3 - j)) * 32);
    }

    // mid buffer: levels 7..16 of e (shift = 13-j)
    float4 wm[NMID];
#pragma unroll
    for (int j = 0; j < NMID; ++j)
        wm[j] = __ldg(Wm1 + (size_t)(b0 >> (13 - j)) * 32);

    // one element; cur = deep rows of e (arrived), refilled with deep(e+2)
    auto body = [&](float4 (&cur)[5]) -> bool {
        // prefetch coll four elements ahead (clamped)
        const int ep4 = e + 4 * stride;
        const int2 cv4 = (ep4 < BATCH) ? __ldg(coll2 + ep4) : make_int2(0, 0);

        const float4 z = cur[0];

        // deep dots (levels 17..20) -> smem
#pragma unroll
        for (int j = 0; j < 4; ++j)
            row[(17 + j) * PITCH + lane] =
                cur[1 + j].x * z.x + cur[1 + j].y * z.y + cur[1 + j].z * z.z + cur[1 + j].w * z.w;

        // shallow JIT levels 0..6 (L1 hits), 4+3 chunks
        {
            float4 h0 = __ldg(Wm1 + (size_t)(b0 >> DEPTH) * 32);
            float4 h1 = __ldg(Wm1 + (size_t)(b0 >> (DEPTH - 1)) * 32);
            float4 h2 = __ldg(Wm1 + (size_t)(b0 >> (DEPTH - 2)) * 32);
            float4 h3 = __ldg(Wm1 + (size_t)(b0 >> (DEPTH - 3)) * 32);
            row[0 * PITCH + lane] = h0.x * z.x + h0.y * z.y + h0.z * z.z + h0.w * z.w;
            row[1 * PITCH + lane] = h1.x * z.x + h1.y * z.y + h1.z * z.z + h1.w * z.w;
            row[2 * PITCH + lane] = h2.x * z.x + h2.y * z.y + h2.z * z.z + h2.w * z.w;
            row[3 * PITCH + lane] = h3.x * z.x + h3.y * z.y + h3.z * z.z + h3.w * z.w;
        }
        {
            float4 h4 = __ldg(Wm1 + (size_t)(b0 >> (DEPTH - 4)) * 32);
            float4 h5 = __ldg(Wm1 + (size_t)(b0 >> (DEPTH - 5)) * 32);
            float4 h6 = __ldg(Wm1 + (size_t)(b0 >> (DEPTH - 6)) * 32);
            row[4 * PITCH + lane] = h4.x * z.x + h4.y * z.y + h4.z * z.z + h4.w * z.w;
            row[5 * PITCH + lane] = h5.x * z.x + h5.y * z.y + h5.z * z.z + h5.w * z.w;
            row[6 * PITCH + lane] = h6.x * z.x + h6.y * z.y + h6.z * z.z + h6.w * z.w;
        }

        // mid dots (levels 7..16) -> smem (frees wm)
#pragma unroll
        for (int j = 0; j < NMID; ++j)
            row[(7 + j) * PITCH + lane] =
                wm[j].x * z.x + wm[j].y * z.y + wm[j].z * z.z + wm[j].w * z.w;

        // issue deep(e+2) into cur (2 iterations of flight)
        {
            const unsigned b2 = (unsigned)cv2.y + OFFSET + 1u;
            cur[0] = __ldg(Wl + (size_t)((unsigned)cv2.x + OFFSET) * 32);
#pragma unroll
            for (int j = 0; j < 4; ++j)
                cur[1 + j] = __ldg(Wm1 + (size_t)(b2 >> (3 - j)) * 32);
        }
        // issue mid(e+1) into wm (1 iteration of flight)
#pragma unroll
        for (int j = 0; j < NMID; ++j)
            wm[j] = __ldg(Wm1 + (size_t)(b1 >> (13 - j)) * 32);

        __syncwarp();

        // lane l (<21) sums its level's 32 partials: 8 x LDS.128
        float c = 1.0f;
        if (lane < NPATH) {
            const float4* r4 = (const float4*)(row + lane * PITCH);
            float4 p0 = r4[0], p1 = r4[1], p2 = r4[2], p3 = r4[3];
            float4 p4 = r4[4], p5 = r4[5], p6 = r4[6], p7 = r4[7];
            float s = ((p0.x + p0.y) + (p0.z + p0.w))
                    + ((p1.x + p1.y) + (p1.z + p1.w))
                    + ((p2.x + p2.y) + (p2.z + p2.w))
                    + ((p3.x + p3.y) + (p3.z + p3.w))
                    + ((p4.x + p4.y) + (p4.z + p4.w))
                    + ((p5.x + p5.y) + (p5.z + p5.w))
                    + ((p6.x + p6.y) + (p6.z + p6.w))
                    + ((p7.x + p7.y) + (p7.z + p7.w));
            c = 1.0f + __expf(-s);
        }
        __syncwarp();   // next iteration's STS must not race these reads

#pragma unroll
        for (int o = 16; o > 0; o >>= 1)
            c *= __shfl_xor_sync(0xFFFFFFFFu, c, o);

        if (lane == 0) out[e] = __fdividef(1.0f, c);

        // advance
        e += stride;
        if (e >= BATCH) return false;
        b0 = b1;
        b1 = (unsigned)cv2.y + OFFSET + 1u;
        cv2 = cv3;
        cv3 = cv4;
        return true;
    };

    for (;;) {
        if (!body(dA)) return;   // even elements consume dA
        if (!body(dB)) return;   // odd elements consume dB
    }
}

extern "C" void kernel_launch(void* const* d_in, const int* in_sizes, int n_in,
                              void* d_out, int out_size)
{
    const int*   coll = (const int*)d_in[0];
    const float* W    = (const float*)d_in[1];
    float*       out  = (float*)d_out;

    // 2-warp blocks; exactly one resident wave sized from measured occupancy.
    const int threads = 64;
    int bpsm = 8;
    cudaOccupancyMaxActiveBlocksPerMultiprocessor(
        &bpsm, BinaryTree_65927747993695_kernel, threads, 0);
    if (bpsm < 1) bpsm = 1;
    long long blocks = (long long)bpsm * 148;
    if (blocks > BATCH / 2) blocks = BATCH / 2;
    BinaryTree_65927747993695_kernel<<<(int)blocks, threads>>>(coll, W, out);
}

// round 15
// speedup vs baseline: 1.0979x; 1.0528x over previous
#include <cuda_runtime.h>
#include <cstdint>

// BinaryTree hierarchical-softmax forward:
//   z = W[leaf(input)], path = 21 root-to-leaf nodes of context vertex
//   out[b] = prod_i sigmoid(dot(W[path_i], z)) = 1 / prod_i (1 + exp(-s_i))
//
// d_in[0]: collocation int32 [65536, 2]
// d_in[1]: W float32 [2097151, 128]
// d_out  : float32 [65536]
//
// R4's exact pipeline (the register-allocator local optimum: full 22-row
// LDG.128 burst for element e+1 issued before e's reduce; 128 regs, no
// spills) plus the one zero-register improvement: prefetch.global.L2 of
// element e+2's true-DRAM rows (z + levels 14..20). Prefetch needs no
// landing register and no ordering, so the deep rows get a full extra
// iteration of flight into L2 — the register burst then sees ~250-cyc L2
// hits instead of exposed DRAM latency. 64-thread blocks so any register
// creep degrades warps/SM by 2, not 4. NO register cap (R5: caps spill).

#define DEPTH   20
#define NPATH   21
#define OFFSET  1048575u             // (1<<DEPTH)-1
#define NDIM    128
#define BATCH   65536

__global__ __launch_bounds__(64)
void BinaryTree_65927747993695_kernel(const int* __restrict__ coll,
                                      const float* __restrict__ W,
                                      float* __restrict__ out)
{
    const int tid    = blockIdx.x * blockDim.x + threadIdx.x;
    const int gw     = tid >> 5;
    const int lane   = tid & 31;
    const int stride = (gridDim.x * blockDim.x) >> 5;

    int e = gw;
    if (e >= BATCH) return;

    const float4* __restrict__ Wl  = (const float4*)W + lane;
    const float4* __restrict__ Wm1 = Wl - (NDIM / 4);   // path "-1" folded in

    // --- prologue ---
    int2 cv0 = __ldg((const int2*)coll + e);
    int  e1  = e + stride;
    int2 cv1 = make_int2(0, 0);
    if (e1 < BATCH) cv1 = __ldg((const int2*)coll + e1);

    float4 z, w[NPATH];
    {
        z = __ldg(Wl + (size_t)((unsigned)cv0.x + OFFSET) * (NDIM / 4));
        const unsigned b = (unsigned)cv0.y + OFFSET + 1u;
#pragma unroll
        for (int i = 0; i < NPATH; ++i)
            w[i] = __ldg(Wm1 + (size_t)(b >> (DEPTH - i)) * (NDIM / 4));
    }

    for (;;) {
        // prefetch coll two elements ahead
        const int e2 = e1 + stride;
        int2 cv2 = make_int2(0, 0);
        if (e2 < BATCH) cv2 = __ldg((const int2*)coll + e2);

        // --- partial dot products for element e (frees w[], z) ---
        float a[32];
#pragma unroll
        for (int i = 0; i < NPATH; ++i)
            a[i] = w[i].x * z.x + w[i].y * z.y + w[i].z * z.z + w[i].w * z.w;
#pragma unroll
        for (int i = NPATH; i < 32; ++i)
            a[i] = 0.0f;

        // --- issue next element's 22-row burst into the freed registers ---
        const bool have_next = (e1 < BATCH);
        if (have_next) {
            z = __ldg(Wl + (size_t)((unsigned)cv1.x + OFFSET) * (NDIM / 4));
            const unsigned b = (unsigned)cv1.y + OFFSET + 1u;
#pragma unroll
            for (int i = 0; i < NPATH; ++i)
                w[i] = __ldg(Wm1 + (size_t)(b >> (DEPTH - i)) * (NDIM / 4));
        }

        // --- zero-register L2 prefetch of e+2's true-DRAM rows ---
        // (z + levels 14..20; fire-and-forget, lands in L2 one extra
        //  iteration before the register burst consumes it)
        if (e2 < BATCH) {
            const unsigned b2 = (unsigned)cv2.y + OFFSET + 1u;
            const float4* pz = Wl + (size_t)((unsigned)cv2.x + OFFSET) * (NDIM / 4);
            asm volatile("prefetch.global.L2 [%0];" :: "l"(pz));
#pragma unroll
            for (int j = 0; j < 7; ++j) {        // levels 14..20: shift 6..0
                const float4* pq = Wm1 + (size_t)(b2 >> (6 - j)) * (NDIM / 4);
                asm volatile("prefetch.global.L2 [%0];" :: "l"(pq));
            }
        }

        // --- compaction transpose-reduce (31 shuffles) overlapping the burst ---
#pragma unroll
        for (int m = 1; m < 32; m <<= 1) {
            const bool hi = (lane & m) != 0;
#pragma unroll
            for (int k = 0; k < 32; k += 2 * m) {
                const float send = hi ? a[k] : a[k + m];
                const float recv = __shfl_xor_sync(0xFFFFFFFFu, send, m);
                a[k] = (hi ? a[k + m] : a[k]) + recv;
            }
        }

        // lane l (< 21) holds s_l; one SIMT EX2 covers all levels
        float c = (lane < NPATH) ? (1.0f + __expf(-a[0])) : 1.0f;
#pragma unroll
        for (int o = 16; o > 0; o >>= 1)
            c *= __shfl_xor_sync(0xFFFFFFFFu, c, o);

        if (lane == 0) out[e] = __fdividef(1.0f, c);

        if (!have_next) return;
        e   = e1;
        e1  = e2;
        cv1 = cv2;
    }
}

extern "C" void kernel_launch(void* const* d_in, const int* in_sizes, int n_in,
                              void* d_out, int out_size)
{
    const int*   coll = (const int*)d_in[0];
    const float* W    = (const float*)d_in[1];
    float*       out  = (float*)d_out;

    // 2-warp blocks; exactly one resident wave sized from measured occupancy.
    const int threads = 64;
    int bpsm = 8;
    cudaOccupancyMaxActiveBlocksPerMultiprocessor(
        &bpsm, BinaryTree_65927747993695_kernel, threads, 0);
    if (bpsm < 1) bpsm = 1;
    long long blocks = (long long)bpsm * 148;
    if (blocks > BATCH / 2) blocks = BATCH / 2;
    BinaryTree_65927747993695_kernel<<<(int)blocks, threads>>>(coll, W, out);
}